// round 11
// baseline (speedup 1.0000x reference)
#include <cuda_runtime.h>

// ChamferLoss: B=8, N=M=4096, C=3, fp32 in, scalar fp32 out.
// Exact NN: z-bin both clouds (counting sort, 256 bins). One WARP per 32
// z-contiguous sources, fully warp-autonomous: scan own bin span, then expand
// outward bin-by-bin, scanning a bin only while ANY lane's current-best radius
// can reach it (ballot). Current best only shrinks, bin z-gap only grows ->
// skip decisions are provably safe -> exact.
// Objective: best = max_t (s.t - |t|^2/2);  d2 = |s|^2 - 2*best.

#define BATCH  8
#define NPTS   4096
#define BN     (BATCH * NPTS)
#define NBINS  256
#define ZLO    (-5.0f)
#define ZW     (10.0f / NBINS)
#define ZINV   (NBINS / 10.0f)

#define WPB        2                       // warps per block
#define THREADS    (32 * WPB)
#define BANDS      128                     // 32-source bands per (dir, batch)
#define TOTAL_WARPS (2 * BATCH * BANDS)    // 2048
#define NN_BLOCKS  (TOTAL_WARPS / WPB)     // 1024

// Binned AoS: [cloud][batch][pos] = (x, y, z, -0.5*|p|^2), bins ascending.
__device__ float4 g_pts[2][BATCH][NPTS];
__device__ int    g_binstart[2][BATCH][NBINS + 1];
__device__ float  g_csum[TOTAL_WARPS];
__device__ int    g_count;  // statically 0; last warp resets for graph replay

// One block per (cloud, batch): histogram -> prefix -> scatter.
__global__ __launch_bounds__(1024)
void build_kernel(const float* __restrict__ f, const float* __restrict__ f_) {
    const int cloud = blockIdx.x >> 3;
    const int b     = blockIdx.x & 7;
    const float* pts = (cloud ? f_ : f) + (size_t)b * NPTS * 3;
    const int tid = threadIdx.x;

    __shared__ int cnt[NBINS], pre[NBINS], offs[NBINS];
    if (tid < NBINS) cnt[tid] = 0;
    __syncthreads();

    int mybin[4];
#pragma unroll
    for (int e = 0; e < 4; e++) {
        int i = tid + e * 1024;
        float z = pts[i * 3 + 2];
        int bin = (int)((z - ZLO) * ZINV);
        bin = min(max(bin, 0), NBINS - 1);
        mybin[e] = bin;
        atomicAdd(&cnt[bin], 1);
    }
    __syncthreads();

    if (tid < NBINS) pre[tid] = cnt[tid];
    __syncthreads();
    for (int s = 1; s < NBINS; s <<= 1) {    // Hillis-Steele inclusive scan
        int v = 0;
        if (tid < NBINS && tid >= s) v = pre[tid - s];
        __syncthreads();
        if (tid < NBINS) pre[tid] += v;
        __syncthreads();
    }
    if (tid < NBINS) {
        int st = pre[tid] - cnt[tid];
        g_binstart[cloud][b][tid] = st;
        offs[tid] = st;
    }
    if (tid == 0) g_binstart[cloud][b][NBINS] = NPTS;
    __syncthreads();

#pragma unroll
    for (int e = 0; e < 4; e++) {
        int i = tid + e * 1024;
        float x = pts[i * 3 + 0], y = pts[i * 3 + 1], z = pts[i * 3 + 2];
        int pos = atomicAdd(&offs[mybin[e]], 1);  // within-bin order arbitrary:
        g_pts[cloud][b][pos] =                    // min over set is unchanged
            make_float4(x, y, z, -0.5f * (x * x + y * y + z * z));
    }
}

__global__ __launch_bounds__(THREADS)
void nn_kernel(float* __restrict__ out) {
    const int wid  = threadIdx.x >> 5;
    const int lane = threadIdx.x & 31;
    const int wgid = blockIdx.x * WPB + wid;     // [0, 2048)
    const int dir  = wgid >> 10;
    const int b    = (wgid >> 7) & 7;
    const int band = wgid & (BANDS - 1);

    const float4* tp = g_pts[1 - dir][b];
    const int*    ts = g_binstart[1 - dir][b];

    __shared__ float4 tile[WPB][32];             // per-warp private tile
    float4* sh = tile[wid];

    // One source per lane; band positions are bin-ascending.
    const float4 s = g_pts[dir][b][band * 32 + lane];
    float bA = -3.402823466e+38f, bB = -3.402823466e+38f;

    // Warp-tile scan of target positions [p0, p1); dual accumulators.
    auto scan = [&](int p0, int p1) {
        for (int base = p0; base < p1; base += 32) {
            int p = base + lane;
            float4 v = (p < p1) ? tp[p]
                                : make_float4(0.f, 0.f, 0.f, -3.402823466e+38f);
            __syncwarp();
            sh[lane] = v;
            __syncwarp();
#pragma unroll
            for (int j = 0; j < 32; j += 2) {
                float4 q0 = sh[j];               // broadcast LDS.128
                float v0 = fmaf(s.x, q0.x, q0.w);
                v0 = fmaf(s.y, q0.y, v0);
                v0 = fmaf(s.z, q0.z, v0);
                bA = fmaxf(bA, v0);
                float4 q1 = sh[j + 1];
                float v1 = fmaf(s.x, q1.x, q1.w);
                v1 = fmaf(s.y, q1.y, v1);
                v1 = fmaf(s.z, q1.z, v1);
                bB = fmaxf(bB, v1);
            }
        }
    };

    int sbin = min(max((int)((s.z - ZLO) * ZINV), 0), NBINS - 1);
    const int minbin = __shfl_sync(0xffffffffu, sbin, 0);    // ascending bins
    const int maxbin = __shfl_sync(0xffffffffu, sbin, 31);

    // Own bin span first (initial upper bounds).
    scan(ts[minbin], ts[maxbin + 1]);

    // Adaptive outward expansion. Bin lb has all z <= ZLO+(lb+1)*ZW (clamped
    // outliers are only farther), so dz is a true lower bound; symmetric right.
    // A bin is skipped only when no lane's CURRENT d2 (valid upper bound of its
    // final d2) can reach it -> exact. Once a side dies it stays dead
    // (dz grows, d2 shrinks).
    int lb = minbin - 1, rb = maxbin + 1;
    bool la = (lb >= 0), ra = (rb < NBINS);
    while (la || ra) {
        if (la) {
            float d2 = -2.0f * (s.w + fmaxf(bA, bB));
            float dz = s.z - (ZLO + (float)(lb + 1) * ZW);
            if (__any_sync(0xffffffffu, dz * dz < d2)) {
                scan(ts[lb], ts[lb + 1]);
                lb--; la = (lb >= 0);
            } else la = false;
        }
        if (ra) {
            float d2 = -2.0f * (s.w + fmaxf(bA, bB));
            float dz = (ZLO + (float)rb * ZW) - s.z;
            if (__any_sync(0xffffffffu, dz * dz < d2)) {
                scan(ts[rb], ts[rb + 1]);
                rb++; ra = (rb < NBINS);
            } else ra = false;
        }
    }

    // Per-lane term = |s|^2 - 2*best; deterministic warp shuffle tree.
    float term = -2.0f * (s.w + fmaxf(bA, bB));
#pragma unroll
    for (int off = 16; off > 0; off >>= 1)
        term += __shfl_down_sync(0xffffffffu, term, off);

    unsigned last = 0;
    if (lane == 0) {
        g_csum[wgid] = term;
        __threadfence();
        last = (atomicAdd(&g_count, 1) == TOTAL_WARPS - 1) ? 1u : 0u;
    }
    last = __shfl_sync(0xffffffffu, last, 0);

    if (last) {
        __threadfence();  // acquire: all g_csum writes visible
        float acc = 0.0f;
#pragma unroll
        for (int kk = 0; kk < TOTAL_WARPS / 32; kk++)   // 64 loads, fixed order
            acc += g_csum[lane + kk * 32];
#pragma unroll
        for (int off = 16; off > 0; off >>= 1)
            acc += __shfl_down_sync(0xffffffffu, acc, off);
        if (lane == 0) {
            out[0] = acc * (1.0f / (float)BN);
            g_count = 0;  // reset for next graph replay
        }
    }
}

extern "C" void kernel_launch(void* const* d_in, const int* in_sizes, int n_in,
                              void* d_out, int out_size) {
    const float* f  = (const float*)d_in[0];
    const float* f_ = (const float*)d_in[1];
    float* out = (float*)d_out;

    build_kernel<<<16, 1024>>>(f, f_);        // 2 clouds x 8 batches
    nn_kernel<<<NN_BLOCKS, THREADS>>>(out);   // 1024 blocks x 64 threads
}

// round 12
// speedup vs baseline: 1.2097x; 1.2097x over previous
#include <cuda_runtime.h>

// ChamferLoss: B=8, N=M=4096, C=3, fp32 in, scalar fp32 out.
// Exact NN: z-bin both clouds (counting sort, 256 bins). One WARP per 32
// z-contiguous sources. Phase A: scan own bin span (widened to >=64 contiguous
// positions -> finite bound) in one sweep. Warp-max d2 -> radius k; Phase B:
// two contiguous side segments covering all bins within k. Bins outside have
// |dz| >= r vs every source in the warp -> provably cannot improve -> exact.
// Objective: best = max_t (s.t - |t|^2/2);  d2 = |s|^2 - 2*best.

#define BATCH  8
#define NPTS   4096
#define BN     (BATCH * NPTS)
#define NBINS  256
#define ZLO    (-5.0f)
#define ZW     (10.0f / NBINS)
#define ZINV   (NBINS / 10.0f)

#define WPB         4                      // warps per block
#define THREADS     (32 * WPB)
#define BANDS       128                    // 32-source bands per (dir, batch)
#define TOTAL_WARPS (2 * BATCH * BANDS)    // 2048
#define NN_BLOCKS   (TOTAL_WARPS / WPB)    // 512

// Binned AoS: [cloud][batch][pos] = (x, y, z, -0.5*|p|^2), bins ascending.
__device__ float4 g_pts[2][BATCH][NPTS];
__device__ int    g_binstart[2][BATCH][NBINS + 1];
__device__ float  g_csum[TOTAL_WARPS];
__device__ int    g_count;  // statically 0; last warp resets for graph replay

// One block per (cloud, batch): histogram -> prefix -> scatter.
__global__ __launch_bounds__(1024)
void build_kernel(const float* __restrict__ f, const float* __restrict__ f_) {
    const int cloud = blockIdx.x >> 3;
    const int b     = blockIdx.x & 7;
    const float* pts = (cloud ? f_ : f) + (size_t)b * NPTS * 3;
    const int tid = threadIdx.x;

    __shared__ int cnt[NBINS], pre[NBINS], offs[NBINS];
    if (tid < NBINS) cnt[tid] = 0;
    __syncthreads();

    int mybin[4];
#pragma unroll
    for (int e = 0; e < 4; e++) {
        int i = tid + e * 1024;
        float z = pts[i * 3 + 2];
        int bin = (int)((z - ZLO) * ZINV);
        bin = min(max(bin, 0), NBINS - 1);
        mybin[e] = bin;
        atomicAdd(&cnt[bin], 1);
    }
    __syncthreads();

    if (tid < NBINS) pre[tid] = cnt[tid];
    __syncthreads();
    for (int s = 1; s < NBINS; s <<= 1) {    // Hillis-Steele inclusive scan
        int v = 0;
        if (tid < NBINS && tid >= s) v = pre[tid - s];
        __syncthreads();
        if (tid < NBINS) pre[tid] += v;
        __syncthreads();
    }
    if (tid < NBINS) {
        int st = pre[tid] - cnt[tid];
        g_binstart[cloud][b][tid] = st;
        offs[tid] = st;
    }
    if (tid == 0) g_binstart[cloud][b][NBINS] = NPTS;
    __syncthreads();

#pragma unroll
    for (int e = 0; e < 4; e++) {
        int i = tid + e * 1024;
        float x = pts[i * 3 + 0], y = pts[i * 3 + 1], z = pts[i * 3 + 2];
        int pos = atomicAdd(&offs[mybin[e]], 1);  // within-bin order arbitrary:
        g_pts[cloud][b][pos] =                    // min over set is unchanged
            make_float4(x, y, z, -0.5f * (x * x + y * y + z * z));
    }
}

__global__ __launch_bounds__(THREADS)
void nn_kernel(float* __restrict__ out) {
    const int wid  = threadIdx.x >> 5;
    const int lane = threadIdx.x & 31;
    const int wgid = blockIdx.x * WPB + wid;     // [0, 2048)
    const int dir  = wgid >> 10;
    const int b    = (wgid >> 7) & 7;
    const int band = wgid & (BANDS - 1);

    const float4* tp = g_pts[1 - dir][b];
    const int*    ts = g_binstart[1 - dir][b];

    __shared__ float4 tile[WPB][32];             // per-warp private tile
    float4* sh = tile[wid];

    // One source per lane; band positions are bin-ascending.
    const float4 s = g_pts[dir][b][band * 32 + lane];
    float bA = -3.402823466e+38f, bB = -3.402823466e+38f;

    // Contiguous warp-tile scan of target positions [p0, p1); dual accumulators
    // break the FMNMX serial chain. Empty range falls out of the guard.
    auto scan = [&](int p0, int p1) {
        for (int base = p0; base < p1; base += 32) {
            int p = base + lane;
            float4 v = (p < p1) ? tp[p]
                                : make_float4(0.f, 0.f, 0.f, -3.402823466e+38f);
            __syncwarp();
            sh[lane] = v;
            __syncwarp();
#pragma unroll
            for (int j = 0; j < 32; j += 2) {
                float4 q0 = sh[j];               // broadcast LDS.128
                float v0 = fmaf(s.x, q0.x, q0.w);
                v0 = fmaf(s.y, q0.y, v0);
                v0 = fmaf(s.z, q0.z, v0);
                bA = fmaxf(bA, v0);
                float4 q1 = sh[j + 1];
                float v1 = fmaf(s.x, q1.x, q1.w);
                v1 = fmaf(s.y, q1.y, v1);
                v1 = fmaf(s.z, q1.z, v1);
                bB = fmaxf(bB, v1);
            }
        }
    };

    int sbin = min(max((int)((s.z - ZLO) * ZINV), 0), NBINS - 1);
    const int minbin = __shfl_sync(0xffffffffu, sbin, 0);    // ascending bins
    const int maxbin = __shfl_sync(0xffffffffu, sbin, 31);

    // Phase A: own bin span, widened to >=64 contiguous positions so the
    // upper bound is always finite.
    int pA0 = ts[minbin], pA1 = ts[maxbin + 1];
    if (pA1 - pA0 < 64) {
        int c = (pA0 + pA1) >> 1;
        pA0 = max(0, min(NPTS - 64, c - 32));
        pA1 = pA0 + 64;
    }
    scan(pA0, pA1);

    // Warp max of d2 = |s|^2 - 2*best: upper bound on every lane's NN dist^2.
    float d2 = -2.0f * (s.w + fmaxf(bA, bB));
#pragma unroll
    for (int off = 16; off > 0; off >>= 1)
        d2 = fmaxf(d2, __shfl_xor_sync(0xffffffffu, d2, off));
    d2 = fmaxf(d2, 0.0f);

    // k*ZW >= r + ZW: any bin outside [lo, hi] has |dz| >= r vs every lane
    // (clamped edge bins only widen true dz) -> cannot improve -> exact.
    const int k = (int)ceilf(__fsqrt_rn(d2) * ZINV) + 1;
    const int lo = max(minbin - k, 0);
    const int hi = min(maxbin + k, NBINS - 1);

    // Phase B: contiguous side segments (everything in range not already
    // covered by the widened phase-A window).
    scan(ts[lo], pA0);
    scan(pA1, ts[hi + 1]);

    // Per-lane term = |s|^2 - 2*best; deterministic warp shuffle tree.
    float term = -2.0f * (s.w + fmaxf(bA, bB));
#pragma unroll
    for (int off = 16; off > 0; off >>= 1)
        term += __shfl_down_sync(0xffffffffu, term, off);

    unsigned last = 0;
    if (lane == 0) {
        g_csum[wgid] = term;
        __threadfence();
        last = (atomicAdd(&g_count, 1) == TOTAL_WARPS - 1) ? 1u : 0u;
    }
    last = __shfl_sync(0xffffffffu, last, 0);

    if (last) {
        __threadfence();  // acquire: all g_csum writes visible
        float acc = 0.0f;
#pragma unroll
        for (int kk = 0; kk < TOTAL_WARPS / 32; kk++)   // 64 loads, fixed order
            acc += g_csum[lane + kk * 32];
#pragma unroll
        for (int off = 16; off > 0; off >>= 1)
            acc += __shfl_down_sync(0xffffffffu, acc, off);
        if (lane == 0) {
            out[0] = acc * (1.0f / (float)BN);
            g_count = 0;  // reset for next graph replay
        }
    }
}

extern "C" void kernel_launch(void* const* d_in, const int* in_sizes, int n_in,
                              void* d_out, int out_size) {
    const float* f  = (const float*)d_in[0];
    const float* f_ = (const float*)d_in[1];
    float* out = (float*)d_out;

    build_kernel<<<16, 1024>>>(f, f_);        // 2 clouds x 8 batches
    nn_kernel<<<NN_BLOCKS, THREADS>>>(out);   // 512 blocks x 128 threads
}

// round 13
// speedup vs baseline: 1.2265x; 1.0139x over previous
#include <cuda_runtime.h>

// ChamferLoss: B=8, N=M=4096, C=3, fp32 in, scalar fp32 out.
// Exact NN: z-bin both clouds (counting sort, 256 bins). One WARP per 32
// z-contiguous sources. Phase A: own bin span (widened to >=64 contiguous
// positions -> finite bound). Then expand outward in 2-bin chunks, re-checking
// per-lane reachability (ballot) EVERY chunk with the current (shrinking)
// bound. A side stops when no lane's current d2 can reach the next bin; dz
// lower bounds grow outward and d2 only shrinks -> stop is final -> exact.
// Objective: best = max_t (s.t - |t|^2/2);  d2 = |s|^2 - 2*best.

#define BATCH  8
#define NPTS   4096
#define BN     (BATCH * NPTS)
#define NBINS  256
#define ZLO    (-5.0f)
#define ZW     (10.0f / NBINS)
#define ZINV   (NBINS / 10.0f)

#define WPB         4                      // warps per block
#define THREADS     (32 * WPB)
#define BANDS       128                    // 32-source bands per (dir, batch)
#define TOTAL_WARPS (2 * BATCH * BANDS)    // 2048
#define NN_BLOCKS   (TOTAL_WARPS / WPB)    // 512

// Binned AoS: [cloud][batch][pos] = (x, y, z, -0.5*|p|^2), bins ascending.
__device__ float4 g_pts[2][BATCH][NPTS];
__device__ int    g_binstart[2][BATCH][NBINS + 1];
__device__ float  g_csum[TOTAL_WARPS];
__device__ int    g_count;  // statically 0; last warp resets for graph replay

// One block per (cloud, batch): histogram -> prefix -> scatter.
__global__ __launch_bounds__(1024)
void build_kernel(const float* __restrict__ f, const float* __restrict__ f_) {
    const int cloud = blockIdx.x >> 3;
    const int b     = blockIdx.x & 7;
    const float* pts = (cloud ? f_ : f) + (size_t)b * NPTS * 3;
    const int tid = threadIdx.x;

    __shared__ int cnt[NBINS], pre[NBINS], offs[NBINS];
    if (tid < NBINS) cnt[tid] = 0;
    __syncthreads();

    int mybin[4];
#pragma unroll
    for (int e = 0; e < 4; e++) {
        int i = tid + e * 1024;
        float z = pts[i * 3 + 2];
        int bin = (int)((z - ZLO) * ZINV);
        bin = min(max(bin, 0), NBINS - 1);
        mybin[e] = bin;
        atomicAdd(&cnt[bin], 1);
    }
    __syncthreads();

    if (tid < NBINS) pre[tid] = cnt[tid];
    __syncthreads();
    for (int s = 1; s < NBINS; s <<= 1) {    // Hillis-Steele inclusive scan
        int v = 0;
        if (tid < NBINS && tid >= s) v = pre[tid - s];
        __syncthreads();
        if (tid < NBINS) pre[tid] += v;
        __syncthreads();
    }
    if (tid < NBINS) {
        int st = pre[tid] - cnt[tid];
        g_binstart[cloud][b][tid] = st;
        offs[tid] = st;
    }
    if (tid == 0) g_binstart[cloud][b][NBINS] = NPTS;
    __syncthreads();

#pragma unroll
    for (int e = 0; e < 4; e++) {
        int i = tid + e * 1024;
        float x = pts[i * 3 + 0], y = pts[i * 3 + 1], z = pts[i * 3 + 2];
        int pos = atomicAdd(&offs[mybin[e]], 1);  // within-bin order arbitrary:
        g_pts[cloud][b][pos] =                    // min over set is unchanged
            make_float4(x, y, z, -0.5f * (x * x + y * y + z * z));
    }
}

__global__ __launch_bounds__(THREADS)
void nn_kernel(float* __restrict__ out) {
    const int wid  = threadIdx.x >> 5;
    const int lane = threadIdx.x & 31;
    const int wgid = blockIdx.x * WPB + wid;     // [0, 2048)
    const int dir  = wgid >> 10;
    const int b    = (wgid >> 7) & 7;
    const int band = wgid & (BANDS - 1);

    const float4* tp = g_pts[1 - dir][b];
    const int*    ts = g_binstart[1 - dir][b];

    __shared__ float4 tile[WPB][32];             // per-warp private tile
    float4* sh = tile[wid];

    // One source per lane; band positions are bin-ascending.
    const float4 s = g_pts[dir][b][band * 32 + lane];
    float bA = -3.402823466e+38f, bB = -3.402823466e+38f;

    // Contiguous warp-tile scan of target positions [p0, p1); dual accumulators.
    auto scan = [&](int p0, int p1) {
        for (int base = p0; base < p1; base += 32) {
            int p = base + lane;
            float4 v = (p < p1) ? tp[p]
                                : make_float4(0.f, 0.f, 0.f, -3.402823466e+38f);
            __syncwarp();
            sh[lane] = v;
            __syncwarp();
#pragma unroll
            for (int j = 0; j < 32; j += 2) {
                float4 q0 = sh[j];               // broadcast LDS.128
                float v0 = fmaf(s.x, q0.x, q0.w);
                v0 = fmaf(s.y, q0.y, v0);
                v0 = fmaf(s.z, q0.z, v0);
                bA = fmaxf(bA, v0);
                float4 q1 = sh[j + 1];
                float v1 = fmaf(s.x, q1.x, q1.w);
                v1 = fmaf(s.y, q1.y, v1);
                v1 = fmaf(s.z, q1.z, v1);
                bB = fmaxf(bB, v1);
            }
        }
    };

    int sbin = min(max((int)((s.z - ZLO) * ZINV), 0), NBINS - 1);
    const int minbin = __shfl_sync(0xffffffffu, sbin, 0);    // ascending bins
    const int maxbin = __shfl_sync(0xffffffffu, sbin, 31);

    // Phase A: own bin span, widened to >=64 contiguous positions so the
    // initial bound is always finite. (Extra coverage may be re-scanned by a
    // chunk later; duplicates are harmless for a max.)
    {
        int pA0 = ts[minbin], pA1 = ts[maxbin + 1];
        if (pA1 - pA0 < 64) {
            int c = (pA0 + pA1) >> 1;
            pA0 = max(0, min(NPTS - 64, c - 32));
            pA1 = pA0 + 64;
        }
        scan(pA0, pA1);
    }

    // Adaptive chunked expansion: scanned span is bins [lb, rb]. Each step
    // re-derives per-lane d2 (current upper bound, only shrinks) and scans a
    // 2-bin chunk on a side only if ANY lane can still reach its nearest bin.
    // Bin lb-1 holds only z <= ZLO + lb*ZW (outlier clamping only widens true
    // |dz|), so dz is a valid lower bound; right side symmetric. Exact.
    int lb = minbin, rb = maxbin;
    bool la = (lb > 0), ra = (rb < NBINS - 1);
    while (la || ra) {
        if (la) {
            float d2 = -2.0f * (s.w + fmaxf(bA, bB));
            float dz = s.z - (ZLO + (float)lb * ZW);
            if (__any_sync(0xffffffffu, dz * dz < d2)) {
                int nl = max(lb - 2, 0);
                scan(ts[nl], ts[lb]);
                lb = nl; la = (lb > 0);
            } else la = false;
        }
        if (ra) {
            float d2 = -2.0f * (s.w + fmaxf(bA, bB));
            float dz = (ZLO + (float)(rb + 1) * ZW) - s.z;
            if (__any_sync(0xffffffffu, dz * dz < d2)) {
                int nr = min(rb + 2, NBINS - 1);
                scan(ts[rb + 1], ts[nr + 1]);
                rb = nr; ra = (rb < NBINS - 1);
            } else ra = false;
        }
    }

    // Per-lane term = |s|^2 - 2*best; deterministic warp shuffle tree.
    float term = -2.0f * (s.w + fmaxf(bA, bB));
#pragma unroll
    for (int off = 16; off > 0; off >>= 1)
        term += __shfl_down_sync(0xffffffffu, term, off);

    unsigned last = 0;
    if (lane == 0) {
        g_csum[wgid] = term;
        __threadfence();
        last = (atomicAdd(&g_count, 1) == TOTAL_WARPS - 1) ? 1u : 0u;
    }
    last = __shfl_sync(0xffffffffu, last, 0);

    if (last) {
        __threadfence();  // acquire: all g_csum writes visible
        float acc = 0.0f;
#pragma unroll
        for (int kk = 0; kk < TOTAL_WARPS / 32; kk++)   // 64 loads, fixed order
            acc += g_csum[lane + kk * 32];
#pragma unroll
        for (int off = 16; off > 0; off >>= 1)
            acc += __shfl_down_sync(0xffffffffu, acc, off);
        if (lane == 0) {
            out[0] = acc * (1.0f / (float)BN);
            g_count = 0;  // reset for next graph replay
        }
    }
}

extern "C" void kernel_launch(void* const* d_in, const int* in_sizes, int n_in,
                              void* d_out, int out_size) {
    const float* f  = (const float*)d_in[0];
    const float* f_ = (const float*)d_in[1];
    float* out = (float*)d_out;

    build_kernel<<<16, 1024>>>(f, f_);        // 2 clouds x 8 batches
    nn_kernel<<<NN_BLOCKS, THREADS>>>(out);   // 512 blocks x 128 threads
}